// round 6
// baseline (speedup 1.0000x reference)
#include <cuda_runtime.h>

// Problem constants (from reference)
#define G_ 4096
#define U_ 50
#define M_ 20
#define D_ 64
#define S_ 64
#define FACTOR_ 0.5f

// 512 threads = 16 warps = 32 half-warp slots; 4 CTAs/SM (100% occupancy).
// Slot s handles user s, and user s+32 when s < 18.
#define NWARPS 16
#define NTHREADS (NWARPS * 32)   // 512
#define SLOTS (NWARPS * 2)       // 32

__global__ __launch_bounds__(NTHREADS, 4)
void group_embedding_kernel(const int*   __restrict__ group_user,      // [G,U]
                            const int*   __restrict__ behavior_ids,    // [G,U,M]
                            const float* __restrict__ behavior_counts, // [G,U,M]
                            const int*   __restrict__ target_user,     // [G]
                            const float* __restrict__ similarity_vec,  // [100000,S]
                            const float* __restrict__ user_emb_w,      // [100000,D]
                            const float* __restrict__ item_emb_w,      // [100000,D]
                            float*       __restrict__ out)             // [G,D]
{
    const int g    = blockIdx.x;
    const int tid  = threadIdx.x;
    const int warp = tid >> 5;
    const int lane = tid & 31;
    const int half = lane >> 4;     // which user of the warp's pair
    const int hl   = lane & 15;     // lane within half-warp: owns dims 4*hl..4*hl+3
    const int slot = warp * 2 + half;   // 0..31

    __shared__ __align__(16) float  partials[SLOTS][D_];  // 8KB
    __shared__ __align__(16) float  red[8][D_];           // 2KB
    // Per-warp behavior pairs: up to 4 users x 20 = 80 (id,count) pairs.
    // Layout: [0,40)  = users 2w, 2w+1   (pass 0)
    //         [40,80) = users 2w+32, 2w+33 (pass 1, only for w <= 8)
    __shared__ __align__(16) float2 wbeh[NWARPS][4 * M_]; // 10KB

    // ---- Per-warp staging (coalesced contiguous segments) ----
    {
        const int base0 = g * (U_ * M_) + warp * (2 * M_);
        wbeh[warp][lane] = make_float2(__int_as_float(behavior_ids[base0 + lane]),
                                       behavior_counts[base0 + lane]);
        if (lane < 8)
            wbeh[warp][32 + lane] =
                make_float2(__int_as_float(behavior_ids[base0 + 32 + lane]),
                            behavior_counts[base0 + 32 + lane]);
        if (warp <= 8) {   // second segment: users 2w+32, 2w+33 (both < 50)
            const int base1 = g * (U_ * M_) + (32 + warp * 2) * M_;
            wbeh[warp][40 + lane] =
                make_float2(__int_as_float(behavior_ids[base1 + lane]),
                            behavior_counts[base1 + lane]);
            if (lane < 8)
                wbeh[warp][72 + lane] =
                    make_float2(__int_as_float(behavior_ids[base1 + 32 + lane]),
                                behavior_counts[base1 + 32 + lane]);
        }
    }

    // Target similarity vector: each half-lane holds 4 consecutive dims.
    const int tgt = target_user[g];
    const float4 tsim = *reinterpret_cast<const float4*>(
        similarity_vec + (size_t)tgt * S_ + 4 * hl);

    __syncwarp();   // own warp's wbeh slice ready

    float4 acc = make_float4(0.f, 0.f, 0.f, 0.f);

    #pragma unroll
    for (int pass = 0; pass < 2; pass++) {
        const int u = slot + 32 * pass;
        if (u >= U_) break;

        const int uid = group_user[g * U_ + u];

        // Early user-embedding load to overlap the gather chain.
        const float4 ue = *reinterpret_cast<const float4*>(
            user_emb_w + (size_t)uid * D_ + 4 * hl);

        // sim = FACTOR * dot(target_sim, other_sim), half-warp reduce.
        const float4 osim = *reinterpret_cast<const float4*>(
            similarity_vec + (size_t)uid * S_ + 4 * hl);
        float dot = tsim.x * osim.x + tsim.y * osim.y
                  + tsim.z * osim.z + tsim.w * osim.w;
        #pragma unroll
        for (int o = 8; o; o >>= 1)
            dot += __shfl_xor_sync(0xffffffffu, dot, o);
        const float sim = FACTOR_ * dot;

        // Weighted sum of item embeddings: 20 independent float4 gathers.
        float4 ub = make_float4(0.f, 0.f, 0.f, 0.f);
        const int bbase = pass * (2 * M_) + half * M_;
        #pragma unroll
        for (int m = 0; m < M_; m++) {
            const float2 p  = wbeh[warp][bbase + m];   // LDS.64 broadcast
            const int    id = __float_as_int(p.x);
            const float  c  = p.y;
            const float4 e  = *reinterpret_cast<const float4*>(
                item_emb_w + (size_t)id * D_ + 4 * hl);
            ub.x += e.x * c;  ub.y += e.y * c;
            ub.z += e.z * c;  ub.w += e.w * c;
        }

        acc.x += ub.x * ue.x * sim;
        acc.y += ub.y * ue.y * sim;
        acc.z += ub.z * ue.z * sim;
        acc.w += ub.w * ue.w * sim;
    }

    *reinterpret_cast<float4*>(&partials[slot][4 * hl]) = acc;
    __syncthreads();

    // ---- Two-stage deterministic reduce over 32 slots ----
    // Stage 1: 512 threads, 8 rows per dim, each sums slots r, r+8, r+16, r+24.
    {
        const int d = tid & 63;
        const int r = tid >> 6;      // 0..7
        float s = 0.f;
        #pragma unroll
        for (int p = r; p < SLOTS; p += 8)
            s += partials[p][d];
        red[r][d] = s;
    }
    __syncthreads();

    // Stage 2: 64 threads fold the 8 rows.
    if (tid < D_) {
        float s = 0.f;
        #pragma unroll
        for (int r = 0; r < 8; r++)
            s += red[r][tid];
        out[(size_t)g * D_ + tid] = s;
    }
}

extern "C" void kernel_launch(void* const* d_in, const int* in_sizes, int n_in,
                              void* d_out, int out_size) {
    const int*   group_user      = (const int*)  d_in[0];
    const int*   behavior_ids    = (const int*)  d_in[1];
    const float* behavior_counts = (const float*)d_in[2];
    const int*   target_user     = (const int*)  d_in[3];
    const float* similarity_vec  = (const float*)d_in[4];
    const float* user_emb_w      = (const float*)d_in[5];
    const float* item_emb_w      = (const float*)d_in[6];
    float* out = (float*)d_out;

    group_embedding_kernel<<<G_, NTHREADS>>>(
        group_user, behavior_ids, behavior_counts, target_user,
        similarity_vec, user_emb_w, item_emb_w, out);
}

// round 7
// speedup vs baseline: 1.0572x; 1.0572x over previous
#include <cuda_runtime.h>

// Problem constants (from reference)
#define G_ 4096
#define U_ 50
#define M_ 20
#define D_ 64
#define S_ 64
#define FACTOR_ 0.5f

// 25 warps = 50 half-warp slots = exactly one user per slot, single pass.
#define NWARPS 25
#define NTHREADS (NWARPS * 32)   // 800
#define SLOTS (NWARPS * 2)       // 50
#define MB 5                     // gather batch depth (explicit MLP)

__global__ __launch_bounds__(NTHREADS, 2)
void group_embedding_kernel(const int*   __restrict__ group_user,      // [G,U]
                            const int*   __restrict__ behavior_ids,    // [G,U,M]
                            const float* __restrict__ behavior_counts, // [G,U,M]
                            const int*   __restrict__ target_user,     // [G]
                            const float* __restrict__ similarity_vec,  // [100000,S]
                            const float* __restrict__ user_emb_w,      // [100000,D]
                            const float* __restrict__ item_emb_w,      // [100000,D]
                            float*       __restrict__ out)             // [G,D]
{
    const int g    = blockIdx.x;
    const int tid  = threadIdx.x;
    const int warp = tid >> 5;
    const int lane = tid & 31;
    const int half = lane >> 4;     // which user of the warp's pair
    const int hl   = lane & 15;     // lane within half-warp: owns dims 4*hl..4*hl+3
    const int slot = warp * 2 + half;   // 0..49 == user index, single pass

    __shared__ __align__(16) float  partials[SLOTS][D_];  // 12.8KB
    __shared__ __align__(16) float  red[8][D_];           // 2KB, stage-1 reduce
    __shared__ __align__(16) float2 wbeh[NWARPS][2 * M_]; // per-warp (id,count), 8KB

    // ---- Per-warp staging: this warp's 2 users' 40 (id,count) pairs.
    {
        const int base = g * (U_ * M_) + warp * (2 * M_);
        wbeh[warp][lane] = make_float2(__int_as_float(behavior_ids[base + lane]),
                                       behavior_counts[base + lane]);
        if (lane < 8)
            wbeh[warp][32 + lane] =
                make_float2(__int_as_float(behavior_ids[base + 32 + lane]),
                            behavior_counts[base + 32 + lane]);
    }

    // This half-warp's user id (broadcast sector).
    const int uid = group_user[g * U_ + slot];

    // Early user-embedding load so it overlaps the gather chain.
    const float4 ue = *reinterpret_cast<const float4*>(
        user_emb_w + (size_t)uid * D_ + 4 * hl);

    // Target similarity vector: each half-lane holds 4 consecutive dims.
    const int tgt = target_user[g];
    const float4 tsim = *reinterpret_cast<const float4*>(
        similarity_vec + (size_t)tgt * S_ + 4 * hl);

    // sim = FACTOR * dot(target_sim, other_sim), half-warp reduce.
    const float4 osim = *reinterpret_cast<const float4*>(
        similarity_vec + (size_t)uid * S_ + 4 * hl);
    float dot = tsim.x * osim.x + tsim.y * osim.y
              + tsim.z * osim.z + tsim.w * osim.w;
    #pragma unroll
    for (int o = 8; o; o >>= 1)
        dot += __shfl_xor_sync(0xffffffffu, dot, o);
    const float sim = FACTOR_ * dot;

    __syncwarp();   // own warp's wbeh slice ready

    // Weighted sum of item embeddings: explicit MB-deep gather batches so
    // MB independent LDG.128s are in flight before any consuming FFMA.
    float4 ub = make_float4(0.f, 0.f, 0.f, 0.f);
    const int bbase = half * M_;
    #pragma unroll
    for (int mb = 0; mb < M_; mb += MB) {
        float  c[MB];
        float4 e[MB];
        #pragma unroll
        for (int j = 0; j < MB; j++) {
            const float2 p = wbeh[warp][bbase + mb + j];  // LDS.64 broadcast
            c[j] = p.y;
            e[j] = *reinterpret_cast<const float4*>(
                item_emb_w + (size_t)__float_as_int(p.x) * D_ + 4 * hl);
        }
        #pragma unroll
        for (int j = 0; j < MB; j++) {
            ub.x += e[j].x * c[j];
            ub.y += e[j].y * c[j];
            ub.z += e[j].z * c[j];
            ub.w += e[j].w * c[j];
        }
    }

    // Personalize with user embedding, weight by sim.
    float4 acc;
    acc.x = ub.x * ue.x * sim;
    acc.y = ub.y * ue.y * sim;
    acc.z = ub.z * ue.z * sim;
    acc.w = ub.w * ue.w * sim;

    *reinterpret_cast<float4*>(&partials[slot][4 * hl]) = acc;
    __syncthreads();

    // ---- Two-stage deterministic reduce over 50 slots ----
    if (tid < 512) {
        const int d = tid & 63;
        const int r = tid >> 6;      // 0..7
        float s = 0.f;
        #pragma unroll
        for (int p = r; p < SLOTS; p += 8)
            s += partials[p][d];
        red[r][d] = s;
    }
    __syncthreads();

    if (tid < D_) {
        float s = 0.f;
        #pragma unroll
        for (int r = 0; r < 8; r++)
            s += red[r][tid];
        out[(size_t)g * D_ + tid] = s;
    }
}

extern "C" void kernel_launch(void* const* d_in, const int* in_sizes, int n_in,
                              void* d_out, int out_size) {
    const int*   group_user      = (const int*)  d_in[0];
    const int*   behavior_ids    = (const int*)  d_in[1];
    const float* behavior_counts = (const float*)d_in[2];
    const int*   target_user     = (const int*)  d_in[3];
    const float* similarity_vec  = (const float*)d_in[4];
    const float* user_emb_w      = (const float*)d_in[5];
    const float* item_emb_w      = (const float*)d_in[6];
    float* out = (float*)d_out;

    group_embedding_kernel<<<G_, NTHREADS>>>(
        group_user, behavior_ids, behavior_counts, target_user,
        similarity_vec, user_emb_w, item_emb_w, out);
}